// round 16
// baseline (speedup 1.0000x reference)
#include <cuda_runtime.h>
#include <cstdint>
#include <cstddef>

// Output depends ONLY on node 1023 of each chain; 5-layer stencil cone spans
// input nodes 1018..1023. One block per graph, full fp32, all in smem.
// GEMVs use float4 weight loads with 4-way k-split + quad shuffle reduction.

__device__ __forceinline__ float leaky(float v) { return (v > 0.f) ? v : 0.01f * v; }
__device__ __forceinline__ float elu(float v)   { return (v > 0.f) ? v : expm1f(v); }

__global__ __launch_bounds__(1024, 1) void cone(
    const float* __restrict__ x,
    const float* __restrict__ Wm1, const float* __restrict__ bm1,
    const float* __restrict__ Ws1, const float* __restrict__ bs1,
    const float* __restrict__ att1,
    const float* __restrict__ Wm2, const float* __restrict__ bm2,
    const float* __restrict__ Ws2, const float* __restrict__ bs2,
    const float* __restrict__ att2,
    const float* __restrict__ Wm3, const float* __restrict__ bm3,
    const float* __restrict__ Ws3, const float* __restrict__ bs3,
    const float* __restrict__ att3,
    const float* __restrict__ Wm4, const float* __restrict__ bm4,
    const float* __restrict__ Ws4, const float* __restrict__ bs4,
    const float* __restrict__ att4,
    const float* __restrict__ Wm5, const float* __restrict__ bm5,
    const float* __restrict__ Ws5, const float* __restrict__ bs5,
    const float* __restrict__ att5,
    const float* __restrict__ Wc,  const float* __restrict__ bc,
    float* __restrict__ out, int out_size)
{
    __shared__ float msg[6][1024];
    __shared__ float wpart[6][32];
    __shared__ float alpha[6][16];     // used by layer 1 only
    __shared__ float wgt[5][32];       // wl[0..15] | wr[16..31]
    __shared__ float xA[6][128];
    __shared__ float xB[5][128];
    __shared__ float selfb[4][128];

    const int tid  = threadIdx.x;
    const int lane = tid & 31;
    const int wrp  = tid >> 5;
    const size_t gb = (size_t)blockIdx.x * 1024;

    if (tid < 6) xA[tid][0] = x[gb + 1018 + tid];
    __syncthreads();

    // ======== Layer 1 (cin=1, H=8, C=128) — unchanged from R15 ========
    {
        const float wm = __ldg(&Wm1[tid]);
        const float bm = __ldg(&bm1[tid]);
        const float at = __ldg(&att1[tid]);
        #pragma unroll
        for (int i = 0; i < 6; i++) {
            const float m = leaky(fmaf(xA[i][0], wm, bm));
            msg[i][tid] = m;
            float p = m * at;
            #pragma unroll
            for (int o = 16; o > 0; o >>= 1) p += __shfl_xor_sync(~0u, p, o);
            if (lane == 0) wpart[i][wrp] = p;
        }
    }
    __syncthreads();
    if (tid < 48) {
        const int i = tid >> 3, h = tid & 7;
        alpha[i][h] = wpart[i][4*h] + wpart[i][4*h+1] + wpart[i][4*h+2] + wpart[i][4*h+3];
    }
    __syncthreads();
    if (tid < 40) {
        const int v = tid >> 3, h = tid & 7, i = v + 1;
        const bool hasR = (i < 5);
        const float al = alpha[i-1][h];
        const float ar = hasR ? alpha[i+1][h] : -1e30f;
        const float mx = fmaxf(al, ar);
        const float el = expf(al - mx);
        const float er = hasR ? expf(ar - mx) : 0.f;
        const float inv = (1.f / ((el + er) + 1e-16f)) * 0.125f;
        wgt[v][h] = el * inv; wgt[v][16+h] = er * inv;
    }
    __syncthreads();
    if (tid < 640) {
        const int v = tid >> 7, c = tid & 127, i = v + 1;
        const int ir = (i < 5) ? i + 1 : i;
        float a = 0.f;
        #pragma unroll
        for (int h = 0; h < 8; h++) {
            a = fmaf(wgt[v][h],    msg[i-1][h*128 + c], a);
            a = fmaf(wgt[v][16+h], msg[ir][h*128 + c],  a);
        }
        a += fmaf(xA[i][0], __ldg(&Ws1[c]), __ldg(&bs1[c]));
        xB[v][c] = elu(a);
    }
    __syncthreads();

    // ======== Layer 2 (cin=128, H=8, C=128); x1 in xB[0..4] ========
    {   // msg2 GEMV: 1024 cols, k-split 4, float4 weights
        const int g4 = tid >> 2, kq = tid & 3;
        const int c0 = g4 * 4;
        float acc[5][4];
        #pragma unroll
        for (int n = 0; n < 5; n++)
            #pragma unroll
            for (int j = 0; j < 4; j++) acc[n][j] = 0.f;
        #pragma unroll 4
        for (int i = 0; i < 32; i++) {
            const int k = 4*i + kq;
            const float4 w = __ldg(reinterpret_cast<const float4*>(Wm2 + (size_t)k*1024 + c0));
            #pragma unroll
            for (int n = 0; n < 5; n++) {
                const float xv = xB[n][k];
                acc[n][0] = fmaf(xv, w.x, acc[n][0]);
                acc[n][1] = fmaf(xv, w.y, acc[n][1]);
                acc[n][2] = fmaf(xv, w.z, acc[n][2]);
                acc[n][3] = fmaf(xv, w.w, acc[n][3]);
            }
        }
        #pragma unroll
        for (int n = 0; n < 5; n++)
            #pragma unroll
            for (int j = 0; j < 4; j++) {
                acc[n][j] += __shfl_xor_sync(~0u, acc[n][j], 1);
                acc[n][j] += __shfl_xor_sync(~0u, acc[n][j], 2);
            }
        if (kq == 0) {
            const float4 bb = __ldg(reinterpret_cast<const float4*>(bm2 + c0));
            #pragma unroll
            for (int n = 0; n < 5; n++) {
                msg[n][c0+0] = leaky(acc[n][0] + bb.x);
                msg[n][c0+1] = leaky(acc[n][1] + bb.y);
                msg[n][c0+2] = leaky(acc[n][2] + bb.z);
                msg[n][c0+3] = leaky(acc[n][3] + bb.w);
            }
        }
    }
    __syncthreads();
    {   // alpha2 pass (all threads)
        const float at = __ldg(&att2[tid]);
        #pragma unroll
        for (int n = 0; n < 5; n++) {
            float p = msg[n][tid] * at;
            #pragma unroll
            for (int o = 16; o > 0; o >>= 1) p += __shfl_xor_sync(~0u, p, o);
            if (lane == 0) wpart[n][wrp] = p;
        }
    }
    if (tid < 512) {   // self2 GEMV: 4 nodes x 128 cols, k-split 4, float4
        const int v = tid >> 7, r = tid & 127;
        const int g4 = r >> 2, kq = r & 3;
        const int c0 = g4 * 4;
        float a0 = 0.f, a1 = 0.f, a2 = 0.f, a3 = 0.f;
        #pragma unroll 4
        for (int i = 0; i < 32; i++) {
            const int k = 4*i + kq;
            const float4 w = __ldg(reinterpret_cast<const float4*>(Ws2 + (size_t)k*128 + c0));
            const float xv = xB[v+1][k];
            a0 = fmaf(xv, w.x, a0); a1 = fmaf(xv, w.y, a1);
            a2 = fmaf(xv, w.z, a2); a3 = fmaf(xv, w.w, a3);
        }
        a0 += __shfl_xor_sync(~0u, a0, 1); a0 += __shfl_xor_sync(~0u, a0, 2);
        a1 += __shfl_xor_sync(~0u, a1, 1); a1 += __shfl_xor_sync(~0u, a1, 2);
        a2 += __shfl_xor_sync(~0u, a2, 1); a2 += __shfl_xor_sync(~0u, a2, 2);
        a3 += __shfl_xor_sync(~0u, a3, 1); a3 += __shfl_xor_sync(~0u, a3, 2);
        if (kq == 0) {
            const float4 bb = __ldg(reinterpret_cast<const float4*>(bs2 + c0));
            selfb[v][c0+0] = a0 + bb.x; selfb[v][c0+1] = a1 + bb.y;
            selfb[v][c0+2] = a2 + bb.z; selfb[v][c0+3] = a3 + bb.w;
        }
    }
    __syncthreads();
    if (tid < 32) {    // wgt for x2 (nodes 1020+v), direct from wpart (H=8: 4 warps/head)
        const int v = tid >> 3, h = tid & 7, i = v + 1;
        const bool hasR = (i < 4);
        const float al = wpart[i-1][4*h] + wpart[i-1][4*h+1] + wpart[i-1][4*h+2] + wpart[i-1][4*h+3];
        const float ar = hasR ? (wpart[i+1][4*h] + wpart[i+1][4*h+1] + wpart[i+1][4*h+2] + wpart[i+1][4*h+3]) : -1e30f;
        const float mx = fmaxf(al, ar);
        const float el = expf(al - mx);
        const float er = hasR ? expf(ar - mx) : 0.f;
        const float inv = (1.f / ((el + er) + 1e-16f)) * 0.125f;
        wgt[v][h] = el * inv; wgt[v][16+h] = er * inv;
    }
    __syncthreads();
    if (tid < 512) {   // x2 at v=0..3 (nodes 1020..1023)
        const int v = tid >> 7, c = tid & 127, i = v + 1;
        const int ir = (i < 4) ? i + 1 : i;
        float a = 0.f;
        #pragma unroll
        for (int h = 0; h < 8; h++) {
            a = fmaf(wgt[v][h],    msg[i-1][h*128 + c], a);
            a = fmaf(wgt[v][16+h], msg[ir][h*128 + c],  a);
        }
        a += selfb[v][c];
        xA[v][c] = elu(a);
    }
    __syncthreads();

    // ======== Layer 3 (cin=128, H=16, C=64); x2 in xA[0..3] ========
    {   // msg3 GEMV: 1024 cols, 4 nodes
        const int g4 = tid >> 2, kq = tid & 3;
        const int c0 = g4 * 4;
        float acc[4][4];
        #pragma unroll
        for (int n = 0; n < 4; n++)
            #pragma unroll
            for (int j = 0; j < 4; j++) acc[n][j] = 0.f;
        #pragma unroll 4
        for (int i = 0; i < 32; i++) {
            const int k = 4*i + kq;
            const float4 w = __ldg(reinterpret_cast<const float4*>(Wm3 + (size_t)k*1024 + c0));
            #pragma unroll
            for (int n = 0; n < 4; n++) {
                const float xv = xA[n][k];
                acc[n][0] = fmaf(xv, w.x, acc[n][0]);
                acc[n][1] = fmaf(xv, w.y, acc[n][1]);
                acc[n][2] = fmaf(xv, w.z, acc[n][2]);
                acc[n][3] = fmaf(xv, w.w, acc[n][3]);
            }
        }
        #pragma unroll
        for (int n = 0; n < 4; n++)
            #pragma unroll
            for (int j = 0; j < 4; j++) {
                acc[n][j] += __shfl_xor_sync(~0u, acc[n][j], 1);
                acc[n][j] += __shfl_xor_sync(~0u, acc[n][j], 2);
            }
        if (kq == 0) {
            const float4 bb = __ldg(reinterpret_cast<const float4*>(bm3 + c0));
            #pragma unroll
            for (int n = 0; n < 4; n++) {
                msg[n][c0+0] = leaky(acc[n][0] + bb.x);
                msg[n][c0+1] = leaky(acc[n][1] + bb.y);
                msg[n][c0+2] = leaky(acc[n][2] + bb.z);
                msg[n][c0+3] = leaky(acc[n][3] + bb.w);
            }
        }
    }
    __syncthreads();
    {   // alpha3 pass
        const float at = __ldg(&att3[tid]);
        #pragma unroll
        for (int n = 0; n < 4; n++) {
            float p = msg[n][tid] * at;
            #pragma unroll
            for (int o = 16; o > 0; o >>= 1) p += __shfl_xor_sync(~0u, p, o);
            if (lane == 0) wpart[n][wrp] = p;
        }
    }
    if (tid < 192) {   // self3 GEMV: 3 nodes x 64 cols, k=128
        const int v = tid >> 6, r = tid & 63;
        const int g4 = r >> 2, kq = r & 3;
        const int c0 = g4 * 4;
        float a0 = 0.f, a1 = 0.f, a2 = 0.f, a3 = 0.f;
        #pragma unroll 4
        for (int i = 0; i < 32; i++) {
            const int k = 4*i + kq;
            const float4 w = __ldg(reinterpret_cast<const float4*>(Ws3 + (size_t)k*64 + c0));
            const float xv = xA[v+1][k];
            a0 = fmaf(xv, w.x, a0); a1 = fmaf(xv, w.y, a1);
            a2 = fmaf(xv, w.z, a2); a3 = fmaf(xv, w.w, a3);
        }
        a0 += __shfl_xor_sync(~0u, a0, 1); a0 += __shfl_xor_sync(~0u, a0, 2);
        a1 += __shfl_xor_sync(~0u, a1, 1); a1 += __shfl_xor_sync(~0u, a1, 2);
        a2 += __shfl_xor_sync(~0u, a2, 1); a2 += __shfl_xor_sync(~0u, a2, 2);
        a3 += __shfl_xor_sync(~0u, a3, 1); a3 += __shfl_xor_sync(~0u, a3, 2);
        if (kq == 0) {
            const float4 bb = __ldg(reinterpret_cast<const float4*>(bs3 + c0));
            selfb[v][c0+0] = a0 + bb.x; selfb[v][c0+1] = a1 + bb.y;
            selfb[v][c0+2] = a2 + bb.z; selfb[v][c0+3] = a3 + bb.w;
        }
    }
    __syncthreads();
    if (tid < 48) {    // wgt for x3 (H=16: 2 warps/head)
        const int v = tid >> 4, h = tid & 15, i = v + 1;
        const bool hasR = (i < 3);
        const float al = wpart[i-1][2*h] + wpart[i-1][2*h+1];
        const float ar = hasR ? (wpart[i+1][2*h] + wpart[i+1][2*h+1]) : -1e30f;
        const float mx = fmaxf(al, ar);
        const float el = expf(al - mx);
        const float er = hasR ? expf(ar - mx) : 0.f;
        const float inv = (1.f / ((el + er) + 1e-16f)) * 0.0625f;
        wgt[v][h] = el * inv; wgt[v][16+h] = er * inv;
    }
    __syncthreads();
    if (tid < 192) {   // x3 at v=0..2, 64-wide
        const int v = tid >> 6, c = tid & 63, i = v + 1;
        const int ir = (i < 3) ? i + 1 : i;
        float a = 0.f;
        #pragma unroll
        for (int h = 0; h < 16; h++) {
            a = fmaf(wgt[v][h],    msg[i-1][h*64 + c], a);
            a = fmaf(wgt[v][16+h], msg[ir][h*64 + c],  a);
        }
        a += selfb[v][c];
        xB[v][c] = elu(a);
    }
    __syncthreads();

    // ======== Layer 4 (cin=64, H=16, C=64); x3 in xB[0..2] ========
    {   // msg4 GEMV: 1024 cols, 3 nodes, k=64
        const int g4 = tid >> 2, kq = tid & 3;
        const int c0 = g4 * 4;
        float acc[3][4];
        #pragma unroll
        for (int n = 0; n < 3; n++)
            #pragma unroll
            for (int j = 0; j < 4; j++) acc[n][j] = 0.f;
        #pragma unroll 4
        for (int i = 0; i < 16; i++) {
            const int k = 4*i + kq;
            const float4 w = __ldg(reinterpret_cast<const float4*>(Wm4 + (size_t)k*1024 + c0));
            #pragma unroll
            for (int n = 0; n < 3; n++) {
                const float xv = xB[n][k];
                acc[n][0] = fmaf(xv, w.x, acc[n][0]);
                acc[n][1] = fmaf(xv, w.y, acc[n][1]);
                acc[n][2] = fmaf(xv, w.z, acc[n][2]);
                acc[n][3] = fmaf(xv, w.w, acc[n][3]);
            }
        }
        #pragma unroll
        for (int n = 0; n < 3; n++)
            #pragma unroll
            for (int j = 0; j < 4; j++) {
                acc[n][j] += __shfl_xor_sync(~0u, acc[n][j], 1);
                acc[n][j] += __shfl_xor_sync(~0u, acc[n][j], 2);
            }
        if (kq == 0) {
            const float4 bb = __ldg(reinterpret_cast<const float4*>(bm4 + c0));
            #pragma unroll
            for (int n = 0; n < 3; n++) {
                msg[n][c0+0] = leaky(acc[n][0] + bb.x);
                msg[n][c0+1] = leaky(acc[n][1] + bb.y);
                msg[n][c0+2] = leaky(acc[n][2] + bb.z);
                msg[n][c0+3] = leaky(acc[n][3] + bb.w);
            }
        }
    }
    __syncthreads();
    {   // alpha4 pass
        const float at = __ldg(&att4[tid]);
        #pragma unroll
        for (int n = 0; n < 3; n++) {
            float p = msg[n][tid] * at;
            #pragma unroll
            for (int o = 16; o > 0; o >>= 1) p += __shfl_xor_sync(~0u, p, o);
            if (lane == 0) wpart[n][wrp] = p;
        }
    }
    if (tid < 128) {   // self4 GEMV: 2 nodes x 64 cols, k=64
        const int v = tid >> 6, r = tid & 63;
        const int g4 = r >> 2, kq = r & 3;
        const int c0 = g4 * 4;
        float a0 = 0.f, a1 = 0.f, a2 = 0.f, a3 = 0.f;
        #pragma unroll 4
        for (int i = 0; i < 16; i++) {
            const int k = 4*i + kq;
            const float4 w = __ldg(reinterpret_cast<const float4*>(Ws4 + (size_t)k*64 + c0));
            const float xv = xB[v+1][k];
            a0 = fmaf(xv, w.x, a0); a1 = fmaf(xv, w.y, a1);
            a2 = fmaf(xv, w.z, a2); a3 = fmaf(xv, w.w, a3);
        }
        a0 += __shfl_xor_sync(~0u, a0, 1); a0 += __shfl_xor_sync(~0u, a0, 2);
        a1 += __shfl_xor_sync(~0u, a1, 1); a1 += __shfl_xor_sync(~0u, a1, 2);
        a2 += __shfl_xor_sync(~0u, a2, 1); a2 += __shfl_xor_sync(~0u, a2, 2);
        a3 += __shfl_xor_sync(~0u, a3, 1); a3 += __shfl_xor_sync(~0u, a3, 2);
        if (kq == 0) {
            const float4 bb = __ldg(reinterpret_cast<const float4*>(bs4 + c0));
            selfb[v][c0+0] = a0 + bb.x; selfb[v][c0+1] = a1 + bb.y;
            selfb[v][c0+2] = a2 + bb.z; selfb[v][c0+3] = a3 + bb.w;
        }
    }
    __syncthreads();
    if (tid < 32) {    // wgt for x4 (H=16)
        const int v = tid >> 4, h = tid & 15, i = v + 1;
        const bool hasR = (i < 2);
        const float al = wpart[i-1][2*h] + wpart[i-1][2*h+1];
        const float ar = hasR ? (wpart[i+1][2*h] + wpart[i+1][2*h+1]) : -1e30f;
        const float mx = fmaxf(al, ar);
        const float el = expf(al - mx);
        const float er = hasR ? expf(ar - mx) : 0.f;
        const float inv = (1.f / ((el + er) + 1e-16f)) * 0.0625f;
        wgt[v][h] = el * inv; wgt[v][16+h] = er * inv;
    }
    __syncthreads();
    if (tid < 128) {   // x4 at v=0..1 (nodes 1022,1023)
        const int v = tid >> 6, c = tid & 63, i = v + 1;
        const int ir = (i < 2) ? i + 1 : i;
        float a = 0.f;
        #pragma unroll
        for (int h = 0; h < 16; h++) {
            a = fmaf(wgt[v][h],    msg[i-1][h*64 + c], a);
            a = fmaf(wgt[v][16+h], msg[ir][h*64 + c],  a);
        }
        a += selfb[v][c];
        xA[v][c] = elu(a);
    }
    __syncthreads();

    // ======== Layer 5 (cin=64, H=1, C=32) + readout ========
    // Node 1023 has a single incoming edge -> softmax weight 1, head-mean identity.
    if (tid < 64) {    // which=0: msg at 1022 (xA[0], Wm5); which=1: self at 1023 (xA[1], Ws5)
        const int which = tid >> 5;
        const int r = tid & 31;
        const int g4 = r >> 2, kq = r & 3;
        const int c0 = g4 * 4;
        const float* W  = which ? Ws5 : Wm5;
        const float* xv = which ? xA[1] : xA[0];
        float a0 = 0.f, a1 = 0.f, a2 = 0.f, a3 = 0.f;
        #pragma unroll 4
        for (int i = 0; i < 16; i++) {
            const int k = 4*i + kq;
            const float4 w = __ldg(reinterpret_cast<const float4*>(W + (size_t)k*32 + c0));
            const float xk = xv[k];
            a0 = fmaf(xk, w.x, a0); a1 = fmaf(xk, w.y, a1);
            a2 = fmaf(xk, w.z, a2); a3 = fmaf(xk, w.w, a3);
        }
        a0 += __shfl_xor_sync(~0u, a0, 1); a0 += __shfl_xor_sync(~0u, a0, 2);
        a1 += __shfl_xor_sync(~0u, a1, 1); a1 += __shfl_xor_sync(~0u, a1, 2);
        a2 += __shfl_xor_sync(~0u, a2, 1); a2 += __shfl_xor_sync(~0u, a2, 2);
        a3 += __shfl_xor_sync(~0u, a3, 1); a3 += __shfl_xor_sync(~0u, a3, 2);
        if (kq == 0) {
            selfb[which][c0+0] = a0; selfb[which][c0+1] = a1;
            selfb[which][c0+2] = a2; selfb[which][c0+3] = a3;
        }
    }
    __syncthreads();
    if (tid < 32) {
        const float m  = leaky(selfb[0][tid] + __ldg(&bm5[tid]));
        const float s  = selfb[1][tid] + __ldg(&bs5[tid]);
        const float o5 = m + s;                       // no ELU on layer 5
        const int fidx = 32 + (int)blockIdx.x * 32 + tid;
        if (fidx < out_size) out[fidx] = o5;
        float p = o5 * __ldg(&Wc[tid]);
        #pragma unroll
        for (int o = 16; o > 0; o >>= 1) p += __shfl_xor_sync(~0u, p, o);
        if (tid == 0 && (int)blockIdx.x < out_size) out[blockIdx.x] = p + __ldg(&bc[0]);
    }
}

// ================= launch =================
extern "C" void kernel_launch(void* const* d_in, const int* in_sizes, int n_in,
                              void* d_out, int out_size)
{
    const float* nodes = (const float*)d_in[0];
    const float* Wm1 = (const float*)d_in[1];  const float* bm1 = (const float*)d_in[2];
    const float* Ws1 = (const float*)d_in[3];  const float* bs1 = (const float*)d_in[4];
    const float* att1 = (const float*)d_in[5];
    const float* Wm2 = (const float*)d_in[6];  const float* bm2 = (const float*)d_in[7];
    const float* Ws2 = (const float*)d_in[8];  const float* bs2 = (const float*)d_in[9];
    const float* att2 = (const float*)d_in[10];
    const float* Wm3 = (const float*)d_in[11]; const float* bm3 = (const float*)d_in[12];
    const float* Ws3 = (const float*)d_in[13]; const float* bs3 = (const float*)d_in[14];
    const float* att3 = (const float*)d_in[15];
    const float* Wm4 = (const float*)d_in[16]; const float* bm4 = (const float*)d_in[17];
    const float* Ws4 = (const float*)d_in[18]; const float* bs4 = (const float*)d_in[19];
    const float* att4 = (const float*)d_in[20];
    const float* Wm5 = (const float*)d_in[21]; const float* bm5 = (const float*)d_in[22];
    const float* Ws5 = (const float*)d_in[23]; const float* bs5 = (const float*)d_in[24];
    const float* att5 = (const float*)d_in[25];
    const float* Wc  = (const float*)d_in[26]; const float* bc  = (const float*)d_in[27];

    cone<<<32, 1024>>>(nodes,
                       Wm1, bm1, Ws1, bs1, att1,
                       Wm2, bm2, Ws2, bs2, att2,
                       Wm3, bm3, Ws3, bs3, att3,
                       Wm4, bm4, Ws4, bs4, att4,
                       Wm5, bm5, Ws5, bs5, att5,
                       Wc, bc, (float*)d_out, out_size);
}